// round 15
// baseline (speedup 1.0000x reference)
#include <cuda_runtime.h>
#include <cuda_fp16.h>
#include <cstdint>
#include <cmath>

#define DX 1024
#define DK 128
#define SEQ 2048
#define NB 8
#define MTOT (NB*SEQ)

__device__ __half g_Wk[DK*DX];
__device__ __half g_Wv[DK*DX];
__device__ __half g_Kh[MTOT*DK];
__device__ __half g_Vh[MTOT*DK];

__device__ __forceinline__ uint32_t sptr(const void* p){
    return (uint32_t)__cvta_generic_to_shared(p);
}
__device__ __forceinline__ void cpa16(uint32_t dst, const void* src){
    asm volatile("cp.async.cg.shared.global [%0], [%1], 16;" :: "r"(dst), "l"(src));
}
__device__ __forceinline__ void cpa_commit(){
    asm volatile("cp.async.commit_group;" ::: "memory");
}
template<int N> __device__ __forceinline__ void cpa_wait(){
    asm volatile("cp.async.wait_group %0;" :: "n"(N) : "memory");
}
__device__ __forceinline__ void ldm4(uint32_t* r, uint32_t a){
    asm volatile("ldmatrix.sync.aligned.m8n8.x4.shared.b16 {%0,%1,%2,%3}, [%4];"
        : "=r"(r[0]),"=r"(r[1]),"=r"(r[2]),"=r"(r[3]) : "r"(a));
}
__device__ __forceinline__ void ldm4t(uint32_t* r, uint32_t a){
    asm volatile("ldmatrix.sync.aligned.m8n8.x4.trans.shared.b16 {%0,%1,%2,%3}, [%4];"
        : "=r"(r[0]),"=r"(r[1]),"=r"(r[2]),"=r"(r[3]) : "r"(a));
}
__device__ __forceinline__ void mma16816(float* c, const uint32_t* a, uint32_t b0, uint32_t b1){
    asm volatile("mma.sync.aligned.m16n8k16.row.col.f32.f16.f16.f32 "
        "{%0,%1,%2,%3}, {%4,%5,%6,%7}, {%8,%9}, {%0,%1,%2,%3};"
        : "+f"(c[0]),"+f"(c[1]),"+f"(c[2]),"+f"(c[3])
        : "r"(a[0]),"r"(a[1]),"r"(a[2]),"r"(a[3]),"r"(b0),"r"(b1));
}
__device__ __forceinline__ float fexp2(float v){
    float r;
    asm("ex2.approx.ftz.f32 %0, %1;" : "=f"(r) : "f"(v));
    return r;
}
__device__ __forceinline__ uint32_t packh2(float a, float b){
    __half2 h = __floats2half2_rn(a, b);
    return *reinterpret_cast<uint32_t*>(&h);
}

// ============================================================
// Kernel 0: convert w_k, w_v to fp16
// ============================================================
__global__ __launch_bounds__(256) void cvtw_kernel(
    const float* __restrict__ wk, const float* __restrict__ wv)
{
    const int NW = DK*DX/4;
    int i = blockIdx.x*256 + threadIdx.x;
    const float* src; __half* dst; int k;
    if (i < NW){ src = wk; dst = g_Wk; k = i; }
    else { src = wv; dst = g_Wv; k = i - NW; }
    float4 v = reinterpret_cast<const float4*>(src)[k];
    uint2 u = make_uint2(packh2(v.x, v.y), packh2(v.z, v.w));
    reinterpret_cast<uint2*>(dst)[k] = u;
}

// ============================================================
// Kernel 1: K/V projection. grid(128, 2); 256 thr, 8 warps x 16 rows.
// x loaded DIRECTLY as A-fragments from global (f32->f16 in regs),
// software-pipelined one k-chunk ahead. W via 3-stage cp.async ring.
// ============================================================
#define PJS 72
#define W_ST (128*PJS)
#define PJ_SMEM (3*W_ST*2)        // 55296 bytes

__global__ __launch_bounds__(256, 2) void proj_kernel(
    const float* __restrict__ x,
    const float* __restrict__ b_k, const float* __restrict__ b_v)
{
    extern __shared__ __half sm[];
    const int tid = threadIdx.x, lane = tid & 31, wid = tid >> 5;
    const int m0 = blockIdx.x * 128;
    const int mat = blockIdx.y;
    const __half* W = mat ? g_Wv : g_Wk;

    auto prefetch = [&](int ki, int s){
        __half* wf = sm + s*W_ST;
        #pragma unroll
        for (int t = 0; t < 4; t++){
            int e = tid + t*256;
            int r = e >> 3, c8 = (e & 7) * 8;
            cpa16(sptr(wf + r*PJS + c8), W + (size_t)r*DX + ki*64 + c8);
        }
        cpa_commit();
    };

    prefetch(0, 0);
    prefetch(1, 1);

    float acc[16][4];
    #pragma unroll
    for (int nt = 0; nt < 16; nt++)
        #pragma unroll
        for (int q = 0; q < 4; q++) acc[nt][q] = 0.f;

    const int fr = lane & 15, fc = (lane >> 4) << 3;
    // A-fragment source rows/cols for this thread
    const int ar = lane >> 2, ac2 = (lane & 3) * 2;
    const float* xrow0 = x + (size_t)(m0 + wid*16 + ar)*DX;
    const float* xrow1 = xrow0 + 8*DX;

    // preload x chunk ki=0 into regs
    float2 v[16];
    #pragma unroll
    for (int ks = 0; ks < 4; ks++){
        int base = ks*16 + ac2;
        v[ks*4+0] = *reinterpret_cast<const float2*>(xrow0 + base);
        v[ks*4+1] = *reinterpret_cast<const float2*>(xrow1 + base);
        v[ks*4+2] = *reinterpret_cast<const float2*>(xrow0 + base + 8);
        v[ks*4+3] = *reinterpret_cast<const float2*>(xrow1 + base + 8);
    }

    int s = 0;
    for (int ki = 0; ki < 16; ki++){
        // pack current x chunk into A fragments
        uint32_t af[4][4];
        #pragma unroll
        for (int ks = 0; ks < 4; ks++)
            #pragma unroll
            for (int q = 0; q < 4; q++)
                af[ks][q] = packh2(v[ks*4+q].x, v[ks*4+q].y);

        // issue next x chunk loads (fly during MMA below)
        if (ki + 1 < 16){
            #pragma unroll
            for (int ks = 0; ks < 4; ks++){
                int base = (ki+1)*64 + ks*16 + ac2;
                v[ks*4+0] = *reinterpret_cast<const float2*>(xrow0 + base);
                v[ks*4+1] = *reinterpret_cast<const float2*>(xrow1 + base);
                v[ks*4+2] = *reinterpret_cast<const float2*>(xrow0 + base + 8);
                v[ks*4+3] = *reinterpret_cast<const float2*>(xrow1 + base + 8);
            }
        }

        cpa_wait<1>();                   // W stage s arrived
        __syncthreads();                 // visible to all; MMA(ki-1) done
        if (ki + 2 < 16) prefetch(ki + 2, (ki + 2) % 3);
        else cpa_commit();

        uint32_t bH = sptr(sm + s*W_ST) + (uint32_t)((fr*PJS + fc)*2);
        #pragma unroll
        for (int kk = 0; kk < 4; kk++){
            #pragma unroll
            for (int np = 0; np < 8; np++){
                uint32_t bh[4];
                ldm4(bh, bH + np*16*PJS*2 + kk*32);
                #pragma unroll
                for (int nn = 0; nn < 2; nn++)
                    mma16816(acc[np*2+nn], af[kk], bh[nn], bh[nn+2]);
            }
        }
        s = (s == 2) ? 0 : s + 1;
    }

    const float* bias = mat ? b_v : b_k;
    __half* outp = mat ? g_Vh : g_Kh;
    const int r0 = lane >> 2, q2 = (lane & 3) << 1;
    size_t grow0 = (size_t)(m0 + wid*16 + r0);
    #pragma unroll
    for (int nt = 0; nt < 16; nt++){
        int col = nt*8 + q2;
        float bb0 = bias[col], bb1 = bias[col+1];
        *reinterpret_cast<__half2*>(outp + grow0*DK + col) =
            __floats2half2_rn(acc[nt][0] + bb0, acc[nt][1] + bb1);
        *reinterpret_cast<__half2*>(outp + (grow0+8)*DK + col) =
            __floats2half2_rn(acc[nt][2] + bb0, acc[nt][3] + bb1);
    }
}

// ============================================================
// Kernel 2: flash attention, full-K, direct output (R14 config).
// grid(32, 8): x = 64-row q tile, y = batch. 32 j-tiles of 64 keys.
// ============================================================
#define AT_S 136
#define A_Q  0
#define A_V0 (64*AT_S)
#define A_V1 (2*64*AT_S)
#define ATTN_SMEM (3*64*AT_S*2)

__global__ __launch_bounds__(128) void attn_kernel(float* __restrict__ out)
{
    extern __shared__ __half sm[];
    const int tid = threadIdx.x, lane = tid & 31, wid = tid >> 5;
    const int b = blockIdx.y, mt = blockIdx.x;
    const size_t kvoff = (size_t)b*SEQ;

    auto prefetchV = [&](int j, int s){
        const __half* gv = g_Vh + (kvoff + (size_t)j*64)*DK;
        __half* base = sm + (s ? A_V1 : A_V0);
        #pragma unroll
        for (int t = 0; t < 8; t++){
            int e = tid + t*128;
            int r = e >> 4, c = (e & 15) * 8;
            cpa16(sptr(base + r*AT_S + c), gv + (size_t)r*DK + c);
        }
    };

    {
        const __half* gq = g_Kh + ((size_t)b*SEQ + (size_t)mt*64)*DK;
        #pragma unroll
        for (int t = 0; t < 8; t++){
            int e = tid + t*128;
            int r = e >> 4, c = (e & 15) * 8;
            cpa16(sptr(sm + A_Q + r*AT_S + c), gq + (size_t)r*DK + c);
        }
        prefetchV(0, 0);
        cpa_commit();
        prefetchV(1, 1);
        cpa_commit();
    }

    const int m0w = wid * 16;
    const int fr = lane & 15, fc = (lane >> 4) << 3;
    const uint32_t smb = sptr(sm);
    const int tr = (lane & 7) + ((lane >> 4) << 3);
    const int tc = ((lane >> 3) & 1) << 3;

    cpa_wait<1>();
    __syncthreads();
    uint32_t qf[8][4];
    {
        const uint32_t aQ = smb + (uint32_t)((A_Q + (m0w+fr)*AT_S + fc)*2);
        #pragma unroll
        for (int kk = 0; kk < 8; kk++) ldm4(qf[kk], aQ + kk*32);
    }

    float o[16][4];
    #pragma unroll
    for (int nt = 0; nt < 16; nt++)
        #pragma unroll
        for (int q = 0; q < 4; q++) o[nt][q] = 0.f;
    float lsum0 = 0.f, lsum1 = 0.f;

    const float cS = 0.08838834764831845f * 1.4426950408889634f;

    for (int j = 0; j < 32; j++){
        const int s = j & 1;
        const uint32_t vb = (uint32_t)((s ? A_V1 : A_V0)*2);
        const uint32_t bV = smb + vb + (uint32_t)((fr*AT_S + fc)*2);
        const uint32_t bO = smb + vb + (uint32_t)((tr*AT_S + tc)*2);

        if (j > 0){
            cpa_wait<1>();
            __syncthreads();
        }

        float s_[8][4];
        #pragma unroll
        for (int nt = 0; nt < 8; nt++)
            #pragma unroll
            for (int q = 0; q < 4; q++) s_[nt][q] = 0.f;

        #pragma unroll
        for (int kk = 0; kk < 8; kk++){
            #pragma unroll
            for (int np = 0; np < 4; np++){
                uint32_t bh[4];
                ldm4(bh, bV + np*16*AT_S*2 + kk*32);
                #pragma unroll
                for (int nn = 0; nn < 2; nn++)
                    mma16816(s_[np*2+nn], qf[kk], bh[nn], bh[nn+2]);
            }
        }

        uint32_t pf[16];
        #pragma unroll
        for (int nt = 0; nt < 8; nt++){
            float p00 = fexp2(s_[nt][0]*cS);
            float p01 = fexp2(s_[nt][1]*cS);
            float p10 = fexp2(s_[nt][2]*cS);
            float p11 = fexp2(s_[nt][3]*cS);
            lsum0 += p00 + p01; lsum1 += p10 + p11;
            pf[nt*2]   = packh2(p00, p01);
            pf[nt*2+1] = packh2(p10, p11);
        }

        #pragma unroll
        for (int kk = 0; kk < 4; kk++){
            const uint32_t* a = pf + kk*4;
            #pragma unroll
            for (int np = 0; np < 8; np++){
                uint32_t bh[4];
                ldm4t(bh, bO + kk*16*AT_S*2 + np*16*2);
                #pragma unroll
                for (int nn = 0; nn < 2; nn++)
                    mma16816(o[np*2+nn], a, bh[nn], bh[nn+2]);
            }
        }
        __syncthreads();
        if (j + 2 < 32) prefetchV(j + 2, s);
        cpa_commit();
    }

    lsum0 += __shfl_xor_sync(0xffffffffu, lsum0, 1);
    lsum0 += __shfl_xor_sync(0xffffffffu, lsum0, 2);
    lsum1 += __shfl_xor_sync(0xffffffffu, lsum1, 1);
    lsum1 += __shfl_xor_sync(0xffffffffu, lsum1, 2);
    const float inv0 = 1.f / lsum0, inv1 = 1.f / lsum1;

    const int r0 = lane >> 2, q2 = (lane & 3) << 1;
    const size_t row0 = (size_t)b*SEQ + (size_t)mt*64 + m0w + r0;
    #pragma unroll
    for (int nt = 0; nt < 16; nt++){
        int col = nt*8 + q2;
        *reinterpret_cast<float2*>(out + row0*DK + col) =
            make_float2(o[nt][0]*inv0, o[nt][1]*inv0);
        *reinterpret_cast<float2*>(out + (row0+8)*DK + col) =
            make_float2(o[nt][2]*inv1, o[nt][3]*inv1);
    }
}

extern "C" void kernel_launch(void* const* d_in, const int* in_sizes, int n_in,
                              void* d_out, int out_size)
{
    const float* x  = (const float*)d_in[0];
    const float* wk = (const float*)d_in[3];
    const float* bk = (const float*)d_in[4];
    const float* wv = (const float*)d_in[5];
    const float* bv = (const float*)d_in[6];
    (void)in_sizes; (void)n_in; (void)out_size;

    cudaFuncSetAttribute(proj_kernel, cudaFuncAttributeMaxDynamicSharedMemorySize, PJ_SMEM);
    cudaFuncSetAttribute(attn_kernel, cudaFuncAttributeMaxDynamicSharedMemorySize, ATTN_SMEM);

    cvtw_kernel<<<256, 256>>>(wk, wv);
    proj_kernel<<<dim3(128,2), 256, PJ_SMEM>>>(x, bk, bv);
    attn_kernel<<<dim3(32,8), 128, ATTN_SMEM>>>((float*)d_out);
}

// round 16
// speedup vs baseline: 1.0619x; 1.0619x over previous
#include <cuda_runtime.h>
#include <cuda_fp16.h>
#include <cstdint>
#include <cmath>

#define DX 1024
#define DK 128
#define SEQ 2048
#define NB 8
#define MTOT (NB*SEQ)

__device__ __half g_Wk[DK*DX];
__device__ __half g_Wv[DK*DX];
__device__ __half g_Kh[MTOT*DK];
__device__ __half g_Vh[MTOT*DK];

__device__ __forceinline__ uint32_t sptr(const void* p){
    return (uint32_t)__cvta_generic_to_shared(p);
}
__device__ __forceinline__ void cpa16(uint32_t dst, const void* src){
    asm volatile("cp.async.cg.shared.global [%0], [%1], 16;" :: "r"(dst), "l"(src));
}
__device__ __forceinline__ void cpa_commit(){
    asm volatile("cp.async.commit_group;" ::: "memory");
}
template<int N> __device__ __forceinline__ void cpa_wait(){
    asm volatile("cp.async.wait_group %0;" :: "n"(N) : "memory");
}
__device__ __forceinline__ void ldm4(uint32_t* r, uint32_t a){
    asm volatile("ldmatrix.sync.aligned.m8n8.x4.shared.b16 {%0,%1,%2,%3}, [%4];"
        : "=r"(r[0]),"=r"(r[1]),"=r"(r[2]),"=r"(r[3]) : "r"(a));
}
__device__ __forceinline__ void ldm4t(uint32_t* r, uint32_t a){
    asm volatile("ldmatrix.sync.aligned.m8n8.x4.trans.shared.b16 {%0,%1,%2,%3}, [%4];"
        : "=r"(r[0]),"=r"(r[1]),"=r"(r[2]),"=r"(r[3]) : "r"(a));
}
__device__ __forceinline__ void mma16816(float* c, const uint32_t* a, uint32_t b0, uint32_t b1){
    asm volatile("mma.sync.aligned.m16n8k16.row.col.f32.f16.f16.f32 "
        "{%0,%1,%2,%3}, {%4,%5,%6,%7}, {%8,%9}, {%0,%1,%2,%3};"
        : "+f"(c[0]),"+f"(c[1]),"+f"(c[2]),"+f"(c[3])
        : "r"(a[0]),"r"(a[1]),"r"(a[2]),"r"(a[3]),"r"(b0),"r"(b1));
}
__device__ __forceinline__ uint32_t packh2(float a, float b){
    __half2 h = __floats2half2_rn(a, b);
    return *reinterpret_cast<uint32_t*>(&h);
}
// P pair = exp2 of (lo, hi) computed in f16x2 — result is the packed A-fragment word
__device__ __forceinline__ uint32_t exp2pair(float lo, float hi){
    uint32_t h, r;
    asm("cvt.rn.f16x2.f32 %0, %1, %2;" : "=r"(h) : "f"(hi), "f"(lo));
    asm("ex2.approx.f16x2 %0, %1;" : "=r"(r) : "r"(h));
    return r;
}

// ============================================================
// Kernel 0: convert w_k, w_v to fp16
// ============================================================
__global__ __launch_bounds__(256) void cvtw_kernel(
    const float* __restrict__ wk, const float* __restrict__ wv)
{
    const int NW = DK*DX/4;
    int i = blockIdx.x*256 + threadIdx.x;
    const float* src; __half* dst; int k;
    if (i < NW){ src = wk; dst = g_Wk; k = i; }
    else { src = wv; dst = g_Wv; k = i - NW; }
    float4 v = reinterpret_cast<const float4*>(src)[k];
    uint2 u = make_uint2(packh2(v.x, v.y), packh2(v.z, v.w));
    reinterpret_cast<uint2*>(dst)[k] = u;
}

// ============================================================
// Kernel 1: K/V projection (R14 config — proven 31us).
// grid(128,2), 256 thr, 8 warps x 16 rows; x LDG->cvt->STS;
// 3-stage W cp.async ring.
// ============================================================
#define PJS 72
#define W_ST (128*PJS)
#define OFF_XH (3*W_ST)
#define PJ_SMEM ((4*W_ST)*2)      // 73728 bytes

__global__ __launch_bounds__(256, 2) void proj_kernel(
    const float* __restrict__ x,
    const float* __restrict__ b_k, const float* __restrict__ b_v)
{
    extern __shared__ __half sm[];
    const int tid = threadIdx.x, lane = tid & 31, wid = tid >> 5;
    const int m0 = blockIdx.x * 128;
    const int mat = blockIdx.y;
    const __half* W = mat ? g_Wv : g_Wk;

    auto prefetch = [&](int ki, int s){
        __half* wf = sm + s*W_ST;
        #pragma unroll
        for (int t = 0; t < 4; t++){
            int e = tid + t*256;
            int r = e >> 3, c8 = (e & 7) * 8;
            cpa16(sptr(wf + r*PJS + c8), W + (size_t)r*DX + ki*64 + c8);
        }
        cpa_commit();
    };

    prefetch(0, 0);
    prefetch(1, 1);

    float acc[16][4];
    #pragma unroll
    for (int nt = 0; nt < 16; nt++)
        #pragma unroll
        for (int q = 0; q < 4; q++) acc[nt][q] = 0.f;

    const int fr = lane & 15, fc = (lane >> 4) << 3;
    __half* xh = sm + OFF_XH;
    const int xr = tid >> 4, xc = (tid & 15) * 4;
    int s = 0;

    for (int ki = 0; ki < 16; ki++){
        cpa_wait<1>();
        float4 v[8];
        #pragma unroll
        for (int t = 0; t < 8; t++)
            v[t] = *reinterpret_cast<const float4*>(
                x + (size_t)(m0 + xr + t*16)*DX + ki*64 + xc);
        __syncthreads();
        if (ki + 2 < 16) prefetch(ki + 2, (ki + 2) % 3);
        else cpa_commit();
        #pragma unroll
        for (int t = 0; t < 8; t++){
            __half* d = xh + (xr + t*16)*PJS + xc;
            *reinterpret_cast<__half2*>(d)     = __floats2half2_rn(v[t].x, v[t].y);
            *reinterpret_cast<__half2*>(d + 2) = __floats2half2_rn(v[t].z, v[t].w);
        }
        __syncthreads();

        uint32_t aH = sptr(xh) + (uint32_t)(((wid*16 + fr)*PJS + fc)*2);
        uint32_t bH = sptr(sm + s*W_ST) + (uint32_t)((fr*PJS + fc)*2);
        #pragma unroll
        for (int kk = 0; kk < 4; kk++){
            uint32_t ah[4];
            ldm4(ah, aH + kk*32);
            #pragma unroll
            for (int np = 0; np < 8; np++){
                uint32_t bh[4];
                ldm4(bh, bH + np*16*PJS*2 + kk*32);
                #pragma unroll
                for (int nn = 0; nn < 2; nn++)
                    mma16816(acc[np*2+nn], ah, bh[nn], bh[nn+2]);
            }
        }
        s = (s == 2) ? 0 : s + 1;
    }

    const float* bias = mat ? b_v : b_k;
    __half* outp = mat ? g_Vh : g_Kh;
    const int r0 = lane >> 2, q2 = (lane & 3) << 1;
    size_t grow0 = (size_t)(m0 + wid*16 + r0);
    #pragma unroll
    for (int nt = 0; nt < 16; nt++){
        int col = nt*8 + q2;
        float bb0 = bias[col], bb1 = bias[col+1];
        *reinterpret_cast<__half2*>(outp + grow0*DK + col) =
            __floats2half2_rn(acc[nt][0] + bb0, acc[nt][1] + bb1);
        *reinterpret_cast<__half2*>(outp + (grow0+8)*DK + col) =
            __floats2half2_rn(acc[nt][2] + bb0, acc[nt][3] + bb1);
    }
}

// ============================================================
// Kernel 2: flash attention, full-K, f16x2 softmax EX2.
// grid(32, 8): x = 64-row q tile, y = batch. 32 j-tiles of 64 keys.
// ============================================================
#define AT_S 136
#define A_Q  0
#define A_V0 (64*AT_S)
#define A_V1 (2*64*AT_S)
#define ATTN_SMEM (3*64*AT_S*2)

__global__ __launch_bounds__(128) void attn_kernel(float* __restrict__ out)
{
    extern __shared__ __half sm[];
    const int tid = threadIdx.x, lane = tid & 31, wid = tid >> 5;
    const int b = blockIdx.y, mt = blockIdx.x;
    const size_t kvoff = (size_t)b*SEQ;

    auto prefetchV = [&](int j, int s){
        const __half* gv = g_Vh + (kvoff + (size_t)j*64)*DK;
        __half* base = sm + (s ? A_V1 : A_V0);
        #pragma unroll
        for (int t = 0; t < 8; t++){
            int e = tid + t*128;
            int r = e >> 4, c = (e & 15) * 8;
            cpa16(sptr(base + r*AT_S + c), gv + (size_t)r*DK + c);
        }
    };

    {
        const __half* gq = g_Kh + ((size_t)b*SEQ + (size_t)mt*64)*DK;
        #pragma unroll
        for (int t = 0; t < 8; t++){
            int e = tid + t*128;
            int r = e >> 4, c = (e & 15) * 8;
            cpa16(sptr(sm + A_Q + r*AT_S + c), gq + (size_t)r*DK + c);
        }
        prefetchV(0, 0);
        cpa_commit();
        prefetchV(1, 1);
        cpa_commit();
    }

    const int m0w = wid * 16;
    const int fr = lane & 15, fc = (lane >> 4) << 3;
    const uint32_t smb = sptr(sm);
    const int tr = (lane & 7) + ((lane >> 4) << 3);
    const int tc = ((lane >> 3) & 1) << 3;

    cpa_wait<1>();
    __syncthreads();
    uint32_t qf[8][4];
    {
        const uint32_t aQ = smb + (uint32_t)((A_Q + (m0w+fr)*AT_S + fc)*2);
        #pragma unroll
        for (int kk = 0; kk < 8; kk++) ldm4(qf[kk], aQ + kk*32);
    }

    float o[16][4];
    #pragma unroll
    for (int nt = 0; nt < 16; nt++)
        #pragma unroll
        for (int q = 0; q < 4; q++) o[nt][q] = 0.f;
    float lsum0 = 0.f, lsum1 = 0.f;

    const float cS = 0.08838834764831845f * 1.4426950408889634f;

    for (int j = 0; j < 32; j++){
        const int s = j & 1;
        const uint32_t vb = (uint32_t)((s ? A_V1 : A_V0)*2);
        const uint32_t bV = smb + vb + (uint32_t)((fr*AT_S + fc)*2);
        const uint32_t bO = smb + vb + (uint32_t)((tr*AT_S + tc)*2);

        if (j > 0){
            cpa_wait<1>();
            __syncthreads();
        }

        float s_[8][4];
        #pragma unroll
        for (int nt = 0; nt < 8; nt++)
            #pragma unroll
            for (int q = 0; q < 4; q++) s_[nt][q] = 0.f;

        #pragma unroll
        for (int kk = 0; kk < 8; kk++){
            #pragma unroll
            for (int np = 0; np < 4; np++){
                uint32_t bh[4];
                ldm4(bh, bV + np*16*AT_S*2 + kk*32);
                #pragma unroll
                for (int nn = 0; nn < 2; nn++)
                    mma16816(s_[np*2+nn], qf[kk], bh[nn], bh[nn+2]);
            }
        }

        // softmax: P = exp2(S*cS) in f16x2 (one MUFU op per pair),
        // result is directly the packed A-fragment word
        uint32_t pf[16];
        #pragma unroll
        for (int nt = 0; nt < 8; nt++){
            uint32_t r0p = exp2pair(s_[nt][0]*cS, s_[nt][1]*cS);
            uint32_t r1p = exp2pair(s_[nt][2]*cS, s_[nt][3]*cS);
            pf[nt*2]   = r0p;
            pf[nt*2+1] = r1p;
            float2 f0 = __half22float2(*reinterpret_cast<__half2*>(&r0p));
            float2 f1 = __half22float2(*reinterpret_cast<__half2*>(&r1p));
            lsum0 += f0.x + f0.y;
            lsum1 += f1.x + f1.y;
        }

        #pragma unroll
        for (int kk = 0; kk < 4; kk++){
            const uint32_t* a = pf + kk*4;
            #pragma unroll
            for (int np = 0; np < 8; np++){
                uint32_t bh[4];
                ldm4t(bh, bO + kk*16*AT_S*2 + np*16*2);
                #pragma unroll
                for (int nn = 0; nn < 2; nn++)
                    mma16816(o[np*2+nn], a, bh[nn], bh[nn+2]);
            }
        }
        __syncthreads();
        if (j + 2 < 32) prefetchV(j + 2, s);
        cpa_commit();
    }

    lsum0 += __shfl_xor_sync(0xffffffffu, lsum0, 1);
    lsum0 += __shfl_xor_sync(0xffffffffu, lsum0, 2);
    lsum1 += __shfl_xor_sync(0xffffffffu, lsum1, 1);
    lsum1 += __shfl_xor_sync(0xffffffffu, lsum1, 2);
    const float inv0 = 1.f / lsum0, inv1 = 1.f / lsum1;

    const int r0 = lane >> 2, q2 = (lane & 3) << 1;
    const size_t row0 = (size_t)b*SEQ + (size_t)mt*64 + m0w + r0;
    #pragma unroll
    for (int nt = 0; nt < 16; nt++){
        int col = nt*8 + q2;
        *reinterpret_cast<float2*>(out + row0*DK + col) =
            make_float2(o[nt][0]*inv0, o[nt][1]*inv0);
        *reinterpret_cast<float2*>(out + (row0+8)*DK + col) =
            make_float2(o[nt][2]*inv1, o[nt][3]*inv1);
    }
}

extern "C" void kernel_launch(void* const* d_in, const int* in_sizes, int n_in,
                              void* d_out, int out_size)
{
    const float* x  = (const float*)d_in[0];
    const float* wk = (const float*)d_in[3];
    const float* bk = (const float*)d_in[4];
    const float* wv = (const float*)d_in[5];
    const float* bv = (const float*)d_in[6];
    (void)in_sizes; (void)n_in; (void)out_size;

    cudaFuncSetAttribute(proj_kernel, cudaFuncAttributeMaxDynamicSharedMemorySize, PJ_SMEM);
    cudaFuncSetAttribute(attn_kernel, cudaFuncAttributeMaxDynamicSharedMemorySize, ATTN_SMEM);

    cvtw_kernel<<<256, 256>>>(wk, wv);
    proj_kernel<<<dim3(128,2), 256, PJ_SMEM>>>(x, bk, bv);
    attn_kernel<<<dim3(32,8), 128, ATTN_SMEM>>>((float*)d_out);
}